// round 1
// baseline (speedup 1.0000x reference)
#include <cuda_runtime.h>

#define BB 64
#define NN 1024
#define KK 8     // 7 knn + self
#define F1 16
#define D1 64    // H1*C1 = 4*16
#define D2 128   // H2*C2 = 4*32

// Scratch (allocation-free rule: __device__ globals)
__device__ float g_xl1[BB * NN * D1];
__device__ float g_xr1[BB * NN * D1];
__device__ float g_h1 [BB * NN * D1];
__device__ float g_xl2[BB * NN * D2];
__device__ float g_xr2[BB * NN * D2];
__device__ float g_h2 [BB * NN * D2];
__device__ int   g_idx[BB * NN * KK];

// ---------------------------------------------------------------------------
// KNN: one batch per blockIdx.y, 256 threads/block, 4 blocks in x cover N=1024.
// pos (+|p|^2) staged in smem as float4; each thread keeps sorted top-7 in regs.
// Distance formula matches reference: |a|^2 + |b|^2 - 2*dot.
// Tie-break matches lax.top_k (stable: earlier index wins on equal distance).
// ---------------------------------------------------------------------------
__global__ void knn_kernel(const float* __restrict__ pos)
{
    __shared__ float4 sp[NN];
    int b = blockIdx.y;
    const float* p = pos + (size_t)b * NN * 3;
    for (int i = threadIdx.x; i < NN; i += blockDim.x) {
        float x = p[i * 3 + 0], y = p[i * 3 + 1], z = p[i * 3 + 2];
        sp[i] = make_float4(x, y, z, x * x + y * y + z * z);
    }
    __syncthreads();

    int n = blockIdx.x * blockDim.x + threadIdx.x;  // node 0..1023
    float4 me = sp[n];

    float bd[7];
    int   bi[7];
#pragma unroll
    for (int j = 0; j < 7; j++) { bd[j] = 3.4028235e38f; bi[j] = 0; }

    for (int m = 0; m < NN; m++) {
        float4 q = sp[m];
        float d = me.w + q.w - 2.f * (me.x * q.x + me.y * q.y + me.z * q.z);
        if (m != n && d < bd[6]) {
            bd[6] = d; bi[6] = m;
#pragma unroll
            for (int j = 6; j > 0; j--) {
                if (bd[j] < bd[j - 1]) {   // strict: ties keep earlier index first
                    float td = bd[j]; bd[j] = bd[j - 1]; bd[j - 1] = td;
                    int   ti = bi[j]; bi[j] = bi[j - 1]; bi[j - 1] = ti;
                }
            }
        }
    }

    int* o = g_idx + ((size_t)((b << 10) + n)) * KK;
#pragma unroll
    for (int j = 0; j < 7; j++) o[j] = bi[j];
    o[7] = n;  // self loop appended last, like the reference
}

// ---------------------------------------------------------------------------
// Fused linear transforms: xl = x@Wl + bl, xr = x@Wr + br.
// One thread per (row, out-col). W's are small and stay L1-resident;
// x-row reads are warp-broadcast.
// ---------------------------------------------------------------------------
template<int FIN, int DOUT>
__global__ void transform_kernel(const float* __restrict__ x,
                                 const float* __restrict__ Wl, const float* __restrict__ bl,
                                 const float* __restrict__ Wr, const float* __restrict__ br,
                                 float* __restrict__ xl, float* __restrict__ xr)
{
    int tid = blockIdx.x * blockDim.x + threadIdx.x;
    int row = tid / DOUT;
    int col = tid - row * DOUT;
    const float* xrow = x + (size_t)row * FIN;
    float al = bl[col];
    float ar = br[col];
#pragma unroll
    for (int k = 0; k < FIN; k++) {
        float xv = xrow[k];
        al = fmaf(xv, Wl[k * DOUT + col], al);
        ar = fmaf(xv, Wr[k * DOUT + col], ar);
    }
    xl[tid] = al;
    xr[tid] = ar;
}

// ---------------------------------------------------------------------------
// GATv2 attention + aggregation, one warp per node.
// Each lane owns V = DOUT/32 consecutive channels; since C (channels/head) is
// 16 or 32 and V is 2 or 4, every lane's channels fall in one head and each
// head is an 8-lane group -> shfl_xor(1,2,4) reduces the logit.
// Neighbors gathered ONCE into registers (KK*V floats), softmax in registers.
// Epilogue: +bias, ReLU.
// ---------------------------------------------------------------------------
template<int C, int DOUT>
__global__ void attn_kernel(const float* __restrict__ xl, const float* __restrict__ xr,
                            const float* __restrict__ att, const float* __restrict__ bias,
                            float* __restrict__ out)
{
    constexpr int V = DOUT / 32;
    int node = (blockIdx.x * blockDim.x + threadIdx.x) >> 5;  // 0 .. B*N-1
    int lane = threadIdx.x & 31;
    int b = node >> 10;
    const int* nidx = g_idx + (size_t)node * KK;

    int c0 = lane * V;
    int h = c0 / C;  // = lane/8

    float xrv[V], attv[V];
#pragma unroll
    for (int v = 0; v < V; v++) {
        xrv[v]  = xr[(size_t)node * DOUT + c0 + v];
        attv[v] = att[c0 + v];  // att laid out [H,C] contiguous == flat [DOUT]
    }

    float xnb[KK][V];
    float lg[KK];
#pragma unroll
    for (int k = 0; k < KK; k++) {
        int src = (b << 10) + nidx[k];
        const float* pp = xl + (size_t)src * DOUT + c0;
        float s = 0.f;
#pragma unroll
        for (int v = 0; v < V; v++) {
            float xv = pp[v];
            xnb[k][v] = xv;
            float e = xv + xrv[v];
            e = e > 0.f ? e : 0.2f * e;           // leaky_relu(0.2)
            s = fmaf(e, attv[v], s);
        }
        s += __shfl_xor_sync(0xffffffffu, s, 1);
        s += __shfl_xor_sync(0xffffffffu, s, 2);
        s += __shfl_xor_sync(0xffffffffu, s, 4);  // logit per head, all 8 lanes
        lg[k] = s;
    }

    // softmax over the K=8 neighborhood
    float mx = lg[0];
#pragma unroll
    for (int k = 1; k < KK; k++) mx = fmaxf(mx, lg[k]);
    float ssum = 0.f;
#pragma unroll
    for (int k = 0; k < KK; k++) { lg[k] = __expf(lg[k] - mx); ssum += lg[k]; }
    float inv = 1.f / ssum;

    float o[V];
#pragma unroll
    for (int v = 0; v < V; v++) o[v] = 0.f;
#pragma unroll
    for (int k = 0; k < KK; k++) {
        float a = lg[k] * inv;
#pragma unroll
        for (int v = 0; v < V; v++) o[v] = fmaf(a, xnb[k][v], o[v]);
    }

#pragma unroll
    for (int v = 0; v < V; v++) {
        float r = o[v] + bias[c0 + v];
        out[(size_t)node * DOUT + c0 + v] = fmaxf(r, 0.f);  // ReLU epilogue
    }
}

// ---------------------------------------------------------------------------
// Global mean pool over N. One block per batch; 512 threads = 4 n-stripes x
// 128 channels; deterministic tree reduction (no atomics).
// ---------------------------------------------------------------------------
__global__ void pool_kernel(const float* __restrict__ h2, float* __restrict__ out)
{
    __shared__ float red[512];
    int b = blockIdx.x;
    int t = threadIdx.x;
    int c = t & 127;
    int s = t >> 7;  // stripe 0..3
    const float* base = h2 + (size_t)b * NN * D2;
    float acc = 0.f;
    int n0 = s * (NN / 4);
#pragma unroll 4
    for (int n = n0; n < n0 + NN / 4; n++) acc += base[(size_t)n * D2 + c];
    red[t] = acc;
    __syncthreads();
    if (s == 0) {
        float r = red[c] + red[c + 128] + red[c + 256] + red[c + 384];
        out[b * D2 + c] = r * (1.f / (float)NN);
    }
}

// ---------------------------------------------------------------------------
extern "C" void kernel_launch(void* const* d_in, const int* in_sizes, int n_in,
                              void* d_out, int out_size)
{
    const float* x     = (const float*)d_in[0];
    const float* pos   = (const float*)d_in[1];
    const float* Wl1   = (const float*)d_in[2];
    const float* bl1   = (const float*)d_in[3];
    const float* Wr1   = (const float*)d_in[4];
    const float* br1   = (const float*)d_in[5];
    const float* att1  = (const float*)d_in[6];
    const float* bias1 = (const float*)d_in[7];
    const float* Wl2   = (const float*)d_in[8];
    const float* bl2   = (const float*)d_in[9];
    const float* Wr2   = (const float*)d_in[10];
    const float* br2   = (const float*)d_in[11];
    const float* att2  = (const float*)d_in[12];
    const float* bias2 = (const float*)d_in[13];
    float* out = (float*)d_out;

    float *xl1, *xr1, *h1, *xl2, *xr2, *h2;
    cudaGetSymbolAddress((void**)&xl1, g_xl1);
    cudaGetSymbolAddress((void**)&xr1, g_xr1);
    cudaGetSymbolAddress((void**)&h1,  g_h1);
    cudaGetSymbolAddress((void**)&xl2, g_xl2);
    cudaGetSymbolAddress((void**)&xr2, g_xr2);
    cudaGetSymbolAddress((void**)&h2,  g_h2);

    // 1) KNN graph
    knn_kernel<<<dim3(NN / 256, BB), 256>>>(pos);

    // 2) Layer-1 transforms, attention, ReLU
    transform_kernel<F1, D1><<<(BB * NN * D1) / 256, 256>>>(x, Wl1, bl1, Wr1, br1, xl1, xr1);
    attn_kernel<16, D1><<<(BB * NN * 32) / 256, 256>>>(xl1, xr1, att1, bias1, h1);

    // 3) Layer-2 transforms, attention, ReLU
    transform_kernel<D1, D2><<<(BB * NN * D2) / 256, 256>>>(h1, Wl2, bl2, Wr2, br2, xl2, xr2);
    attn_kernel<32, D2><<<(BB * NN * 32) / 256, 256>>>(xl2, xr2, att2, bias2, h2);

    // 4) Global mean pool
    pool_kernel<<<BB, 512>>>(h2, out);
}

// round 2
// speedup vs baseline: 1.2113x; 1.2113x over previous
#include <cuda_runtime.h>

#define BB 64
#define NN 1024
#define KK 8     // 7 knn + self
#define F1 16
#define D1 64    // H1*C1 = 4*16
#define D2 128   // H2*C2 = 4*32

typedef unsigned long long ull;

// Scratch (allocation-free rule: __device__ globals)
__device__ float g_xl1[BB * NN * D1];
__device__ float g_xr1[BB * NN * D1];
__device__ float g_h1 [BB * NN * D1];
__device__ float g_xl2[BB * NN * D2];
__device__ float g_xr2[BB * NN * D2];
__device__ float g_h2 [BB * NN * D2];
__device__ int   g_idx[BB * NN * KK];

// Packed dual-fp32 FMA (sm_103a f32x2 pipe — ptxas never emits this from C++)
__device__ __forceinline__ ull fma2(ull a, ull b, ull c) {
    ull d;
    asm("fma.rn.f32x2 %0, %1, %2, %3;" : "=l"(d) : "l"(a), "l"(b), "l"(c));
    return d;
}
__device__ __forceinline__ ull bcast2(float v) {
    ull d;
    asm("mov.b64 %0, {%1, %1};" : "=l"(d) : "r"(__float_as_uint(v)));
    return d;
}

// ---------------------------------------------------------------------------
// KNN: one batch per blockIdx.y, 256 threads/block, 4 blocks in x cover N=1024.
// ---------------------------------------------------------------------------
__global__ void knn_kernel(const float* __restrict__ pos)
{
    __shared__ float4 sp[NN];
    int b = blockIdx.y;
    const float* p = pos + (size_t)b * NN * 3;
    for (int i = threadIdx.x; i < NN; i += blockDim.x) {
        float x = p[i * 3 + 0], y = p[i * 3 + 1], z = p[i * 3 + 2];
        sp[i] = make_float4(x, y, z, x * x + y * y + z * z);
    }
    __syncthreads();

    int n = blockIdx.x * blockDim.x + threadIdx.x;  // node 0..1023
    float4 me = sp[n];

    float bd[7];
    int   bi[7];
#pragma unroll
    for (int j = 0; j < 7; j++) { bd[j] = 3.4028235e38f; bi[j] = 0; }

    for (int m = 0; m < NN; m++) {
        float4 q = sp[m];
        float d = me.w + q.w - 2.f * (me.x * q.x + me.y * q.y + me.z * q.z);
        if (m != n && d < bd[6]) {
            bd[6] = d; bi[6] = m;
#pragma unroll
            for (int j = 6; j > 0; j--) {
                if (bd[j] < bd[j - 1]) {   // strict: ties keep earlier index first
                    float td = bd[j]; bd[j] = bd[j - 1]; bd[j - 1] = td;
                    int   ti = bi[j]; bi[j] = bi[j - 1]; bi[j - 1] = ti;
                }
            }
        }
    }

    int* o = g_idx + ((size_t)((b << 10) + n)) * KK;
#pragma unroll
    for (int j = 0; j < 7; j++) o[j] = bi[j];
    o[7] = n;  // self loop appended last, like the reference
}

// ---------------------------------------------------------------------------
// Transform GEMM: out = x @ W + b for ONE matrix (grid.y picks Wl or Wr).
// W + bias staged in smem (<=32KB). One thread per row; x row in registers;
// 32-col chunks with 16 packed f32x2 accumulators; W read via broadcast
// LDS.128. FMA-pipe bound (fma.rn.f32x2 = 2 fp32 FMA / instr).
// ---------------------------------------------------------------------------
template<int FIN, int DOUT>
__global__ void __launch_bounds__(256, 2) transform_kernel(
    const float* __restrict__ x,
    const float* __restrict__ Wa, const float* __restrict__ ba,
    const float* __restrict__ Wb, const float* __restrict__ bb,
    float* __restrict__ outa, float* __restrict__ outb)
{
    __shared__ float Ws[FIN * DOUT];
    __shared__ float sb[DOUT];

    const float* W    = blockIdx.y ? Wb   : Wa;
    const float* bias = blockIdx.y ? bb   : ba;
    float*       out  = blockIdx.y ? outb : outa;

    for (int i = threadIdx.x; i < FIN * DOUT; i += 256) Ws[i] = W[i];
    if (threadIdx.x < DOUT) sb[threadIdx.x] = bias[threadIdx.x];
    __syncthreads();

    int row = blockIdx.x * 256 + threadIdx.x;

    float xreg[FIN];
    const float4* x4 = (const float4*)(x + (size_t)row * FIN);
#pragma unroll
    for (int i = 0; i < FIN / 4; i++) {
        float4 t = x4[i];
        xreg[4 * i + 0] = t.x; xreg[4 * i + 1] = t.y;
        xreg[4 * i + 2] = t.z; xreg[4 * i + 3] = t.w;
    }

    float* orow = out + (size_t)row * DOUT;

#pragma unroll 1
    for (int j = 0; j < DOUT / 32; j++) {           // 32-col chunk
        int cbase = j * 32;
        ull acc[16];
        const ull* bp = (const ull*)(sb + cbase);
#pragma unroll
        for (int q = 0; q < 16; q++) acc[q] = bp[q];

#pragma unroll
        for (int k = 0; k < FIN; k++) {
            ull xv2 = bcast2(xreg[k]);
            const ulonglong2* wp = (const ulonglong2*)(Ws + k * DOUT + cbase);
#pragma unroll
            for (int q4 = 0; q4 < 4; q4++) {        // 4x LDS.128 (broadcast)
                ulonglong2 w = wp[q4];
                acc[q4 * 4 + 0] = fma2(xv2, w.x, acc[q4 * 4 + 0]);
                acc[q4 * 4 + 1] = fma2(xv2, w.y, acc[q4 * 4 + 1]);
                // next 16B
                ulonglong2 w2 = wp[q4];             // placeholder overwritten below
                (void)w2;
                break;
            }
            // unrolled explicitly for all 8 ulonglong pairs:
            const ull* wq = (const ull*)(Ws + k * DOUT + cbase);
#pragma unroll
            for (int q = 2; q < 16; q++) acc[q] = fma2(xv2, wq[q], acc[q]);
        }

        ull* op = (ull*)(orow + cbase);
#pragma unroll
        for (int q = 0; q < 16; q++) op[q] = acc[q];
    }
}

// Clean version of the inner loop (the above had an editing artifact).
// Specialization used instead:
template<int FIN, int DOUT>
__global__ void __launch_bounds__(256, 2) transform_kernel2(
    const float* __restrict__ x,
    const float* __restrict__ Wa, const float* __restrict__ ba,
    const float* __restrict__ Wb, const float* __restrict__ bb,
    float* __restrict__ outa, float* __restrict__ outb)
{
    __shared__ float Ws[FIN * DOUT];
    __shared__ float sb[DOUT];

    const float* W    = blockIdx.y ? Wb   : Wa;
    const float* bias = blockIdx.y ? bb   : ba;
    float*       out  = blockIdx.y ? outb : outa;

    for (int i = threadIdx.x; i < FIN * DOUT; i += 256) Ws[i] = W[i];
    if (threadIdx.x < DOUT) sb[threadIdx.x] = bias[threadIdx.x];
    __syncthreads();

    int row = blockIdx.x * 256 + threadIdx.x;

    float xreg[FIN];
    const float4* x4 = (const float4*)(x + (size_t)row * FIN);
#pragma unroll
    for (int i = 0; i < FIN / 4; i++) {
        float4 t = x4[i];
        xreg[4 * i + 0] = t.x; xreg[4 * i + 1] = t.y;
        xreg[4 * i + 2] = t.z; xreg[4 * i + 3] = t.w;
    }

    float* orow = out + (size_t)row * DOUT;

#pragma unroll 1
    for (int j = 0; j < DOUT / 32; j++) {
        int cbase = j * 32;
        ull acc[16];
        const ull* bp = (const ull*)(sb + cbase);
#pragma unroll
        for (int q = 0; q < 16; q++) acc[q] = bp[q];

#pragma unroll
        for (int k = 0; k < FIN; k++) {
            ull xv2 = bcast2(xreg[k]);
            const ulonglong2* wp = (const ulonglong2*)(Ws + k * DOUT + cbase);
#pragma unroll
            for (int q4 = 0; q4 < 8; q4++) {     // 8x LDS.128 per k? no: 8x ulonglong2 = 8 LDS.128
                ulonglong2 w = wp[q4];
                acc[q4 * 2 + 0] = fma2(xv2, w.x, acc[q4 * 2 + 0]);
                acc[q4 * 2 + 1] = fma2(xv2, w.y, acc[q4 * 2 + 1]);
            }
        }

        ull* op = (ull*)(orow + cbase);
#pragma unroll
        for (int q = 0; q < 16; q++) op[q] = acc[q];
    }
}

// ---------------------------------------------------------------------------
// GATv2 attention + aggregation, one warp per node (unchanged from R0).
// ---------------------------------------------------------------------------
template<int C, int DOUT>
__global__ void attn_kernel(const float* __restrict__ xl, const float* __restrict__ xr,
                            const float* __restrict__ att, const float* __restrict__ bias,
                            float* __restrict__ out)
{
    constexpr int V = DOUT / 32;
    int node = (blockIdx.x * blockDim.x + threadIdx.x) >> 5;
    int lane = threadIdx.x & 31;
    int b = node >> 10;
    const int* nidx = g_idx + (size_t)node * KK;

    int c0 = lane * V;

    float xrv[V], attv[V];
#pragma unroll
    for (int v = 0; v < V; v++) {
        xrv[v]  = xr[(size_t)node * DOUT + c0 + v];
        attv[v] = att[c0 + v];
    }

    float xnb[KK][V];
    float lg[KK];
#pragma unroll
    for (int k = 0; k < KK; k++) {
        int src = (b << 10) + nidx[k];
        const float* pp = xl + (size_t)src * DOUT + c0;
        float s = 0.f;
#pragma unroll
        for (int v = 0; v < V; v++) {
            float xv = pp[v];
            xnb[k][v] = xv;
            float e = xv + xrv[v];
            e = e > 0.f ? e : 0.2f * e;
            s = fmaf(e, attv[v], s);
        }
        s += __shfl_xor_sync(0xffffffffu, s, 1);
        s += __shfl_xor_sync(0xffffffffu, s, 2);
        s += __shfl_xor_sync(0xffffffffu, s, 4);
        lg[k] = s;
    }

    float mx = lg[0];
#pragma unroll
    for (int k = 1; k < KK; k++) mx = fmaxf(mx, lg[k]);
    float ssum = 0.f;
#pragma unroll
    for (int k = 0; k < KK; k++) { lg[k] = __expf(lg[k] - mx); ssum += lg[k]; }
    float inv = 1.f / ssum;

    float o[V];
#pragma unroll
    for (int v = 0; v < V; v++) o[v] = 0.f;
#pragma unroll
    for (int k = 0; k < KK; k++) {
        float a = lg[k] * inv;
#pragma unroll
        for (int v = 0; v < V; v++) o[v] = fmaf(a, xnb[k][v], o[v]);
    }

#pragma unroll
    for (int v = 0; v < V; v++) {
        float r = o[v] + bias[c0 + v];
        out[(size_t)node * DOUT + c0 + v] = fmaxf(r, 0.f);
    }
}

// ---------------------------------------------------------------------------
// Global mean pool over N (unchanged).
// ---------------------------------------------------------------------------
__global__ void pool_kernel(const float* __restrict__ h2, float* __restrict__ out)
{
    __shared__ float red[512];
    int b = blockIdx.x;
    int t = threadIdx.x;
    int c = t & 127;
    int s = t >> 7;
    const float* base = h2 + (size_t)b * NN * D2;
    float acc = 0.f;
    int n0 = s * (NN / 4);
#pragma unroll 4
    for (int n = n0; n < n0 + NN / 4; n++) acc += base[(size_t)n * D2 + c];
    red[t] = acc;
    __syncthreads();
    if (s == 0) {
        float r = red[c] + red[c + 128] + red[c + 256] + red[c + 384];
        out[b * D2 + c] = r * (1.f / (float)NN);
    }
}

// ---------------------------------------------------------------------------
extern "C" void kernel_launch(void* const* d_in, const int* in_sizes, int n_in,
                              void* d_out, int out_size)
{
    const float* x     = (const float*)d_in[0];
    const float* pos   = (const float*)d_in[1];
    const float* Wl1   = (const float*)d_in[2];
    const float* bl1   = (const float*)d_in[3];
    const float* Wr1   = (const float*)d_in[4];
    const float* br1   = (const float*)d_in[5];
    const float* att1  = (const float*)d_in[6];
    const float* bias1 = (const float*)d_in[7];
    const float* Wl2   = (const float*)d_in[8];
    const float* bl2   = (const float*)d_in[9];
    const float* Wr2   = (const float*)d_in[10];
    const float* br2   = (const float*)d_in[11];
    const float* att2  = (const float*)d_in[12];
    const float* bias2 = (const float*)d_in[13];
    float* out = (float*)d_out;

    float *xl1, *xr1, *h1, *xl2, *xr2, *h2;
    cudaGetSymbolAddress((void**)&xl1, g_xl1);
    cudaGetSymbolAddress((void**)&xr1, g_xr1);
    cudaGetSymbolAddress((void**)&h1,  g_h1);
    cudaGetSymbolAddress((void**)&xl2, g_xl2);
    cudaGetSymbolAddress((void**)&xr2, g_xr2);
    cudaGetSymbolAddress((void**)&h2,  g_h2);

    // 1) KNN graph
    knn_kernel<<<dim3(NN / 256, BB), 256>>>(pos);

    // 2) Layer-1 transforms (grid.y: 0 -> Wl/xl, 1 -> Wr/xr), attention, ReLU
    transform_kernel2<F1, D1><<<dim3(BB * NN / 256, 2), 256>>>(
        x, Wl1, bl1, Wr1, br1, xl1, xr1);
    attn_kernel<16, D1><<<(BB * NN * 32) / 256, 256>>>(xl1, xr1, att1, bias1, h1);

    // 3) Layer-2 transforms, attention, ReLU
    transform_kernel2<D1, D2><<<dim3(BB * NN / 256, 2), 256>>>(
        h1, Wl2, bl2, Wr2, br2, xl2, xr2);
    attn_kernel<32, D2><<<(BB * NN * 32) / 256, 256>>>(xl2, xr2, att2, bias2, h2);

    // 4) Global mean pool
    pool_kernel<<<BB, 512>>>(h2, out);
}

// round 3
// speedup vs baseline: 1.4503x; 1.1972x over previous
#include <cuda_runtime.h>

#define BB 64
#define NN 1024
#define KK 8     // 7 knn + self
#define F1 16
#define D1 64    // H1*C1 = 4*16
#define D2 128   // H2*C2 = 4*32

typedef unsigned long long ull;

// Scratch (allocation-free rule: __device__ globals)
__device__ float g_xl1[BB * NN * D1];
__device__ float g_xr1[BB * NN * D1];
__device__ float g_h1 [BB * NN * D1];
__device__ float g_xl2[BB * NN * D2];
__device__ float g_xr2[BB * NN * D2];
__device__ float g_h2 [BB * NN * D2];
__device__ int   g_idx[BB * NN * KK];

// Packed dual-fp32 FMA (sm_103a f32x2 pipe — ptxas never emits this from C++)
__device__ __forceinline__ ull fma2(ull a, ull b, ull c) {
    ull d;
    asm("fma.rn.f32x2 %0, %1, %2, %3;" : "=l"(d) : "l"(a), "l"(b), "l"(c));
    return d;
}
__device__ __forceinline__ ull bcast2(float v) {
    ull d;
    asm("mov.b64 %0, {%1, %1};" : "=l"(d) : "r"(__float_as_uint(v)));
    return d;
}

// ---------------------------------------------------------------------------
// KNN: one batch per blockIdx.y, 256 threads/block, 4 blocks in x cover N=1024.
// ---------------------------------------------------------------------------
__global__ void knn_kernel(const float* __restrict__ pos)
{
    __shared__ float4 sp[NN];
    int b = blockIdx.y;
    const float* p = pos + (size_t)b * NN * 3;
    for (int i = threadIdx.x; i < NN; i += blockDim.x) {
        float x = p[i * 3 + 0], y = p[i * 3 + 1], z = p[i * 3 + 2];
        sp[i] = make_float4(x, y, z, x * x + y * y + z * z);
    }
    __syncthreads();

    int n = blockIdx.x * blockDim.x + threadIdx.x;  // node 0..1023
    float4 me = sp[n];

    float bd[7];
    int   bi[7];
#pragma unroll
    for (int j = 0; j < 7; j++) { bd[j] = 3.4028235e38f; bi[j] = 0; }

    for (int m = 0; m < NN; m++) {
        float4 q = sp[m];
        float d = me.w + q.w - 2.f * (me.x * q.x + me.y * q.y + me.z * q.z);
        if (m != n && d < bd[6]) {
            bd[6] = d; bi[6] = m;
#pragma unroll
            for (int j = 6; j > 0; j--) {
                if (bd[j] < bd[j - 1]) {   // strict: ties keep earlier index first
                    float td = bd[j]; bd[j] = bd[j - 1]; bd[j - 1] = td;
                    int   ti = bi[j]; bi[j] = bi[j - 1]; bi[j - 1] = ti;
                }
            }
        }
    }

    int* o = g_idx + ((size_t)((b << 10) + n)) * KK;
#pragma unroll
    for (int j = 0; j < 7; j++) o[j] = bi[j];
    o[7] = n;  // self loop appended last, like the reference
}

// ---------------------------------------------------------------------------
// Register-blocked GEMM: out = x @ W + b for ONE matrix (grid.y picks Wl/Wr).
// Block tile: 128 rows x DOUT cols, 256 threads = 16(tx) x 16(ty).
// Thread tile: 8 rows x (DOUT/16) cols, accumulated in packed f32x2 regs.
// x tile staged TRANSPOSED + value-duplicated ({v,v} per ull) in smem so the
// inner loop is pure LDS.128 + fma.rn.f32x2: per k -> 4 LDS(x) + <=2 LDS(W)
// feeding 8*(DOUT/32) fma2. Padded strides avoid bank conflicts.
// ---------------------------------------------------------------------------
template<int FIN, int DOUT>
__global__ void __launch_bounds__(256) gemm_kernel(
    const float* __restrict__ x,
    const float* __restrict__ Wa, const float* __restrict__ ba,
    const float* __restrict__ Wb, const float* __restrict__ bb,
    float* __restrict__ outa, float* __restrict__ outb)
{
    constexpr int CT = DOUT / 16;   // cols per thread (floats): 4 or 8
    constexpr int CU = CT / 2;      // packed accumulators per row: 2 or 4
    constexpr int RX = 130;         // xs row stride (ull): 128 rows + pad
    constexpr int RW = DOUT + 4;    // ws row stride (floats)

    __shared__ ull   xs[FIN * RX];
    __shared__ float ws[FIN * RW];
    __shared__ float sb[DOUT];

    const float* W    = blockIdx.y ? Wb   : Wa;
    const float* bias = blockIdx.y ? bb   : ba;
    float*       out  = blockIdx.y ? outb : outa;

    int tid  = threadIdx.x;
    int base = blockIdx.x * 128;

    // Stage W (padded rows) and bias
    for (int i = tid; i < FIN * DOUT; i += 256) {
        int k = i / DOUT, c = i - k * DOUT;
        ws[k * RW + c] = W[i];
    }
    if (tid < DOUT) sb[tid] = bias[tid];
    // Stage x tile transposed, each value duplicated into both f32x2 lanes
    for (int i = tid; i < 128 * FIN; i += 256) {
        int r = i / FIN, k = i - r * FIN;
        xs[k * RX + r] = bcast2(x[(size_t)(base + r) * FIN + k]);
    }
    __syncthreads();

    int tx = tid & 15, ty = tid >> 4;
    int r0 = ty * 8, c0 = tx * CT;

    ull acc[8][CU];
    {
        const ull* bp = (const ull*)(sb + c0);
#pragma unroll
        for (int r = 0; r < 8; r++)
#pragma unroll
            for (int c = 0; c < CU; c++) acc[r][c] = bp[c];
    }

#pragma unroll 4
    for (int k = 0; k < FIN; k++) {
        ull xv[8];
        const ulonglong2* xp = (const ulonglong2*)(xs + k * RX + r0);
#pragma unroll
        for (int i = 0; i < 4; i++) {
            ulonglong2 t = xp[i];
            xv[2 * i] = t.x; xv[2 * i + 1] = t.y;
        }
        ull wv[CU];
        const ulonglong2* wp = (const ulonglong2*)(ws + k * RW + c0);
#pragma unroll
        for (int c = 0; c < CU / 2; c++) {
            ulonglong2 t = wp[c];
            wv[2 * c] = t.x; wv[2 * c + 1] = t.y;
        }
#pragma unroll
        for (int r = 0; r < 8; r++)
#pragma unroll
            for (int c = 0; c < CU; c++)
                acc[r][c] = fma2(xv[r], wv[c], acc[r][c]);
    }

#pragma unroll
    for (int r = 0; r < 8; r++) {
        ulonglong2* op = (ulonglong2*)(out + (size_t)(base + r0 + r) * DOUT + c0);
#pragma unroll
        for (int c = 0; c < CU / 2; c++)
            op[c] = make_ulonglong2(acc[r][2 * c], acc[r][2 * c + 1]);
    }
}

// ---------------------------------------------------------------------------
// GATv2 attention + aggregation, one warp per node (unchanged).
// ---------------------------------------------------------------------------
template<int C, int DOUT>
__global__ void attn_kernel(const float* __restrict__ xl, const float* __restrict__ xr,
                            const float* __restrict__ att, const float* __restrict__ bias,
                            float* __restrict__ out)
{
    constexpr int V = DOUT / 32;
    int node = (blockIdx.x * blockDim.x + threadIdx.x) >> 5;
    int lane = threadIdx.x & 31;
    int b = node >> 10;
    const int* nidx = g_idx + (size_t)node * KK;

    int c0 = lane * V;

    float xrv[V], attv[V];
#pragma unroll
    for (int v = 0; v < V; v++) {
        xrv[v]  = xr[(size_t)node * DOUT + c0 + v];
        attv[v] = att[c0 + v];
    }

    float xnb[KK][V];
    float lg[KK];
#pragma unroll
    for (int k = 0; k < KK; k++) {
        int src = (b << 10) + nidx[k];
        const float* pp = xl + (size_t)src * DOUT + c0;
        float s = 0.f;
#pragma unroll
        for (int v = 0; v < V; v++) {
            float xv = pp[v];
            xnb[k][v] = xv;
            float e = xv + xrv[v];
            e = e > 0.f ? e : 0.2f * e;
            s = fmaf(e, attv[v], s);
        }
        s += __shfl_xor_sync(0xffffffffu, s, 1);
        s += __shfl_xor_sync(0xffffffffu, s, 2);
        s += __shfl_xor_sync(0xffffffffu, s, 4);
        lg[k] = s;
    }

    float mx = lg[0];
#pragma unroll
    for (int k = 1; k < KK; k++) mx = fmaxf(mx, lg[k]);
    float ssum = 0.f;
#pragma unroll
    for (int k = 0; k < KK; k++) { lg[k] = __expf(lg[k] - mx); ssum += lg[k]; }
    float inv = 1.f / ssum;

    float o[V];
#pragma unroll
    for (int v = 0; v < V; v++) o[v] = 0.f;
#pragma unroll
    for (int k = 0; k < KK; k++) {
        float a = lg[k] * inv;
#pragma unroll
        for (int v = 0; v < V; v++) o[v] = fmaf(a, xnb[k][v], o[v]);
    }

#pragma unroll
    for (int v = 0; v < V; v++) {
        float r = o[v] + bias[c0 + v];
        out[(size_t)node * DOUT + c0 + v] = fmaxf(r, 0.f);
    }
}

// ---------------------------------------------------------------------------
// Global mean pool over N (unchanged).
// ---------------------------------------------------------------------------
__global__ void pool_kernel(const float* __restrict__ h2, float* __restrict__ out)
{
    __shared__ float red[512];
    int b = blockIdx.x;
    int t = threadIdx.x;
    int c = t & 127;
    int s = t >> 7;
    const float* base = h2 + (size_t)b * NN * D2;
    float acc = 0.f;
    int n0 = s * (NN / 4);
#pragma unroll 4
    for (int n = n0; n < n0 + NN / 4; n++) acc += base[(size_t)n * D2 + c];
    red[t] = acc;
    __syncthreads();
    if (s == 0) {
        float r = red[c] + red[c + 128] + red[c + 256] + red[c + 384];
        out[b * D2 + c] = r * (1.f / (float)NN);
    }
}

// ---------------------------------------------------------------------------
extern "C" void kernel_launch(void* const* d_in, const int* in_sizes, int n_in,
                              void* d_out, int out_size)
{
    const float* x     = (const float*)d_in[0];
    const float* pos   = (const float*)d_in[1];
    const float* Wl1   = (const float*)d_in[2];
    const float* bl1   = (const float*)d_in[3];
    const float* Wr1   = (const float*)d_in[4];
    const float* br1   = (const float*)d_in[5];
    const float* att1  = (const float*)d_in[6];
    const float* bias1 = (const float*)d_in[7];
    const float* Wl2   = (const float*)d_in[8];
    const float* bl2   = (const float*)d_in[9];
    const float* Wr2   = (const float*)d_in[10];
    const float* br2   = (const float*)d_in[11];
    const float* att2  = (const float*)d_in[12];
    const float* bias2 = (const float*)d_in[13];
    float* out = (float*)d_out;

    float *xl1, *xr1, *h1, *xl2, *xr2, *h2;
    cudaGetSymbolAddress((void**)&xl1, g_xl1);
    cudaGetSymbolAddress((void**)&xr1, g_xr1);
    cudaGetSymbolAddress((void**)&h1,  g_h1);
    cudaGetSymbolAddress((void**)&xl2, g_xl2);
    cudaGetSymbolAddress((void**)&xr2, g_xr2);
    cudaGetSymbolAddress((void**)&h2,  g_h2);

    // 1) KNN graph
    knn_kernel<<<dim3(NN / 256, BB), 256>>>(pos);

    // 2) Layer-1 transforms (grid.y: 0 -> Wl/xl, 1 -> Wr/xr), attention, ReLU
    gemm_kernel<F1, D1><<<dim3(BB * NN / 128, 2), 256>>>(
        x, Wl1, bl1, Wr1, br1, xl1, xr1);
    attn_kernel<16, D1><<<(BB * NN * 32) / 256, 256>>>(xl1, xr1, att1, bias1, h1);

    // 3) Layer-2 transforms, attention, ReLU
    gemm_kernel<D1, D2><<<dim3(BB * NN / 128, 2), 256>>>(
        h1, Wl2, bl2, Wr2, br2, xl2, xr2);
    attn_kernel<32, D2><<<(BB * NN * 32) / 256, 256>>>(xl2, xr2, att2, bias2, h2);

    // 4) Global mean pool
    pool_kernel<<<BB, 512>>>(h2, out);
}

// round 4
// speedup vs baseline: 1.7162x; 1.1834x over previous
#include <cuda_runtime.h>

#define BB 64
#define NN 1024
#define KK 8     // 7 knn + self
#define F1 16
#define D1 64    // H1*C1 = 4*16
#define D2 128   // H2*C2 = 4*32

typedef unsigned long long ull;

// Scratch (allocation-free rule: __device__ globals)
__device__ float g_xl1[BB * NN * D1];
__device__ float g_xr1[BB * NN * D1];
__device__ float g_h1 [BB * NN * D1];
__device__ float g_xl2[BB * NN * D2];
__device__ float g_xr2[BB * NN * D2];
__device__ float g_h2 [BB * NN * D2];
__device__ int   g_idx[BB * NN * KK];

// Packed dual-fp32 FMA (sm_103a f32x2 pipe — ptxas never emits this from C++)
__device__ __forceinline__ ull fma2(ull a, ull b, ull c) {
    ull d;
    asm("fma.rn.f32x2 %0, %1, %2, %3;" : "=l"(d) : "l"(a), "l"(b), "l"(c));
    return d;
}
__device__ __forceinline__ ull bcast2(float v) {
    ull d;
    asm("mov.b64 %0, {%1, %1};" : "=l"(d) : "r"(__float_as_uint(v)));
    return d;
}

// ---------------------------------------------------------------------------
// KNN: one batch per blockIdx.y, 256 threads/block, 4 blocks in x cover N=1024.
// ---------------------------------------------------------------------------
__global__ void knn_kernel(const float* __restrict__ pos)
{
    __shared__ float4 sp[NN];
    int b = blockIdx.y;
    const float* p = pos + (size_t)b * NN * 3;
    for (int i = threadIdx.x; i < NN; i += blockDim.x) {
        float x = p[i * 3 + 0], y = p[i * 3 + 1], z = p[i * 3 + 2];
        sp[i] = make_float4(x, y, z, x * x + y * y + z * z);
    }
    __syncthreads();

    int n = blockIdx.x * blockDim.x + threadIdx.x;  // node 0..1023
    float4 me = sp[n];

    float bd[7];
    int   bi[7];
#pragma unroll
    for (int j = 0; j < 7; j++) { bd[j] = 3.4028235e38f; bi[j] = 0; }

#pragma unroll 2
    for (int m = 0; m < NN; m++) {
        float4 q = sp[m];
        float d = me.w + q.w - 2.f * (me.x * q.x + me.y * q.y + me.z * q.z);
        if (m != n && d < bd[6]) {
            bd[6] = d; bi[6] = m;
#pragma unroll
            for (int j = 6; j > 0; j--) {
                if (bd[j] < bd[j - 1]) {   // strict: ties keep earlier index first
                    float td = bd[j]; bd[j] = bd[j - 1]; bd[j - 1] = td;
                    int   ti = bi[j]; bi[j] = bi[j - 1]; bi[j - 1] = ti;
                }
            }
        }
    }

    int* o = g_idx + ((size_t)((b << 10) + n)) * KK;
#pragma unroll
    for (int j = 0; j < 7; j++) o[j] = bi[j];
    o[7] = n;  // self loop appended last, like the reference
}

// ---------------------------------------------------------------------------
// Register-blocked GEMM: out = x @ W + b for ONE matrix (grid.y picks Wl/Wr).
// Block tile: 128 rows x DOUT cols, 256 threads = 16(tx) x 16(ty).
// Thread tile: 8 rows x (DOUT/16) cols in packed f32x2 accumulators.
// x staged TRANSPOSED as plain float; per k the 8 row-values come in as
// 2x LDS.128 (float4) and are lane-duplicated via mov.b64 (ALU pipe, overlaps
// FMA pipe). W packed naturally (2 adjacent cols per ull). Per k-step:
// 4 LDS.128 (16 crossbar cyc/SM) feeding 32 fma2 (16 fma cyc/SM) — balanced.
// ---------------------------------------------------------------------------
template<int FIN, int DOUT>
__global__ void __launch_bounds__(256) gemm_kernel(
    const float* __restrict__ x,
    const float* __restrict__ Wa, const float* __restrict__ ba,
    const float* __restrict__ Wb, const float* __restrict__ bb,
    float* __restrict__ outa, float* __restrict__ outb)
{
    constexpr int CT  = DOUT / 16;   // cols per thread (floats): 4 or 8
    constexpr int CU  = CT / 2;      // packed accumulators per row: 2 or 4
    constexpr int RXf = 132;         // xs row stride (floats): 128 + 4 (16B-aligned)
    constexpr int RW  = DOUT + 4;    // ws row stride (floats), 16B-aligned

    __shared__ float xs[FIN * RXf];
    __shared__ float ws[FIN * RW];
    __shared__ float sb[DOUT];

    const float* W    = blockIdx.y ? Wb   : Wa;
    const float* bias = blockIdx.y ? bb   : ba;
    float*       out  = blockIdx.y ? outb : outa;

    int tid  = threadIdx.x;
    int base = blockIdx.x * 128;

    // Stage W (padded rows) and bias
    for (int i = tid; i < FIN * DOUT; i += 256) {
        int k = i / DOUT, c = i - k * DOUT;
        ws[k * RW + c] = W[i];
    }
    if (tid < DOUT) sb[tid] = bias[tid];
    // Stage x tile transposed (coalesced LDG; STS conflicts amortized)
    for (int i = tid; i < 128 * FIN; i += 256) {
        int r = i / FIN, k = i - r * FIN;
        xs[k * RXf + r] = x[(size_t)(base + r) * FIN + k];
    }
    __syncthreads();

    int tx = tid & 15, ty = tid >> 4;
    int r0 = ty * 8, c0 = tx * CT;

    ull acc[8][CU];
    {
        const ull* bp = (const ull*)(sb + c0);
#pragma unroll
        for (int r = 0; r < 8; r++)
#pragma unroll
            for (int c = 0; c < CU; c++) acc[r][c] = bp[c];
    }

#pragma unroll 4
    for (int k = 0; k < FIN; k++) {
        const float4* xp = (const float4*)(xs + k * RXf + r0);
        float4 xa = xp[0], xb = xp[1];
        ull xv[8];
        xv[0] = bcast2(xa.x); xv[1] = bcast2(xa.y);
        xv[2] = bcast2(xa.z); xv[3] = bcast2(xa.w);
        xv[4] = bcast2(xb.x); xv[5] = bcast2(xb.y);
        xv[6] = bcast2(xb.z); xv[7] = bcast2(xb.w);

        ull wv[CU];
        const ulonglong2* wp = (const ulonglong2*)(ws + k * RW + c0);
#pragma unroll
        for (int c = 0; c < CU / 2; c++) {
            ulonglong2 t = wp[c];
            wv[2 * c] = t.x; wv[2 * c + 1] = t.y;
        }
#pragma unroll
        for (int r = 0; r < 8; r++)
#pragma unroll
            for (int c = 0; c < CU; c++)
                acc[r][c] = fma2(xv[r], wv[c], acc[r][c]);
    }

#pragma unroll
    for (int r = 0; r < 8; r++) {
        ulonglong2* op = (ulonglong2*)(out + (size_t)(base + r0 + r) * DOUT + c0);
#pragma unroll
        for (int c = 0; c < CU / 2; c++)
            op[c] = make_ulonglong2(acc[r][2 * c], acc[r][2 * c + 1]);
    }
}

// ---------------------------------------------------------------------------
// GATv2 attention + aggregation, one warp per node; vectorized loads/stores.
// ---------------------------------------------------------------------------
template<int C, int DOUT>
__global__ void attn_kernel(const float* __restrict__ xl, const float* __restrict__ xr,
                            const float* __restrict__ att, const float* __restrict__ bias,
                            float* __restrict__ out)
{
    constexpr int V = DOUT / 32;   // 2 or 4
    int node = (blockIdx.x * blockDim.x + threadIdx.x) >> 5;
    int lane = threadIdx.x & 31;
    int b = node >> 10;
    const int* nidx = g_idx + (size_t)node * KK;

    int c0 = lane * V;

    float xrv[V], attv[V];
    if constexpr (V == 4) {
        float4 t = *(const float4*)(xr + (size_t)node * DOUT + c0);
        xrv[0] = t.x; xrv[1] = t.y; xrv[2] = t.z; xrv[3] = t.w;
        float4 a = *(const float4*)(att + c0);
        attv[0] = a.x; attv[1] = a.y; attv[2] = a.z; attv[3] = a.w;
    } else {
        float2 t = *(const float2*)(xr + (size_t)node * DOUT + c0);
        xrv[0] = t.x; xrv[1] = t.y;
        float2 a = *(const float2*)(att + c0);
        attv[0] = a.x; attv[1] = a.y;
    }

    float xnb[KK][V];
    float lg[KK];
#pragma unroll
    for (int k = 0; k < KK; k++) {
        int src = (b << 10) + nidx[k];
        const float* pp = xl + (size_t)src * DOUT + c0;
        if constexpr (V == 4) {
            float4 t = *(const float4*)pp;
            xnb[k][0] = t.x; xnb[k][1] = t.y; xnb[k][2] = t.z; xnb[k][3] = t.w;
        } else {
            float2 t = *(const float2*)pp;
            xnb[k][0] = t.x; xnb[k][1] = t.y;
        }
        float s = 0.f;
#pragma unroll
        for (int v = 0; v < V; v++) {
            float e = xnb[k][v] + xrv[v];
            e = e > 0.f ? e : 0.2f * e;       // leaky_relu(0.2)
            s = fmaf(e, attv[v], s);
        }
        s += __shfl_xor_sync(0xffffffffu, s, 1);
        s += __shfl_xor_sync(0xffffffffu, s, 2);
        s += __shfl_xor_sync(0xffffffffu, s, 4);
        lg[k] = s;
    }

    float mx = lg[0];
#pragma unroll
    for (int k = 1; k < KK; k++) mx = fmaxf(mx, lg[k]);
    float ssum = 0.f;
#pragma unroll
    for (int k = 0; k < KK; k++) { lg[k] = __expf(lg[k] - mx); ssum += lg[k]; }
    float inv = 1.f / ssum;

    float o[V];
#pragma unroll
    for (int v = 0; v < V; v++) o[v] = 0.f;
#pragma unroll
    for (int k = 0; k < KK; k++) {
        float a = lg[k] * inv;
#pragma unroll
        for (int v = 0; v < V; v++) o[v] = fmaf(a, xnb[k][v], o[v]);
    }

    float* po = out + (size_t)node * DOUT + c0;
    if constexpr (V == 4) {
        float4 bv = *(const float4*)(bias + c0);
        float4 r;
        r.x = fmaxf(o[0] + bv.x, 0.f);
        r.y = fmaxf(o[1] + bv.y, 0.f);
        r.z = fmaxf(o[2] + bv.z, 0.f);
        r.w = fmaxf(o[3] + bv.w, 0.f);
        *(float4*)po = r;
    } else {
        float2 bv = *(const float2*)(bias + c0);
        float2 r;
        r.x = fmaxf(o[0] + bv.x, 0.f);
        r.y = fmaxf(o[1] + bv.y, 0.f);
        *(float2*)po = r;
    }
}

// ---------------------------------------------------------------------------
// Global mean pool over N. One block per batch; float4 per thread.
// 512 threads = 16 n-stripes x 32 float4-columns; tree reduction in smem.
// ---------------------------------------------------------------------------
__global__ void pool_kernel(const float* __restrict__ h2, float* __restrict__ out)
{
    __shared__ float4 red[512];
    int b = blockIdx.x;
    int t = threadIdx.x;
    int c = t & 31;          // float4 column 0..31 (covers 128 floats)
    int s = t >> 5;          // stripe 0..15
    const float4* base = (const float4*)(h2 + (size_t)b * NN * D2);
    float4 acc = make_float4(0.f, 0.f, 0.f, 0.f);
#pragma unroll 4
    for (int n = s * (NN / 16); n < (s + 1) * (NN / 16); n++) {
        float4 v = base[n * 32 + c];
        acc.x += v.x; acc.y += v.y; acc.z += v.z; acc.w += v.w;
    }
    red[t] = acc;
    __syncthreads();
#pragma unroll
    for (int step = 256; step >= 32; step >>= 1) {
        if (t < step) {
            float4 o = red[t + step];
            float4 m = red[t];
            m.x += o.x; m.y += o.y; m.z += o.z; m.w += o.w;
            red[t] = m;
        }
        __syncthreads();
    }
    if (t < 32) {
        float4 m = red[t];
        const float inv = 1.f / (float)NN;
        ((float4*)(out + b * D2))[t] =
            make_float4(m.x * inv, m.y * inv, m.z * inv, m.w * inv);
    }
}

// ---------------------------------------------------------------------------
extern "C" void kernel_launch(void* const* d_in, const int* in_sizes, int n_in,
                              void* d_out, int out_size)
{
    const float* x     = (const float*)d_in[0];
    const float* pos   = (const float*)d_in[1];
    const float* Wl1   = (const float*)d_in[2];
    const float* bl1   = (const float*)d_in[3];
    const float* Wr1   = (const float*)d_in[4];
    const float* br1   = (const float*)d_in[5];
    const float* att1  = (const float*)d_in[6];
    const float* bias1 = (const float*)d_in[7];
    const float* Wl2   = (const float*)d_in[8];
    const float* bl2   = (const float*)d_in[9];
    const float* Wr2   = (const float*)d_in[10];
    const float* br2   = (const float*)d_in[11];
    const float* att2  = (const float*)d_in[12];
    const float* bias2 = (const float*)d_in[13];
    float* out = (float*)d_out;

    float *xl1, *xr1, *h1, *xl2, *xr2, *h2;
    cudaGetSymbolAddress((void**)&xl1, g_xl1);
    cudaGetSymbolAddress((void**)&xr1, g_xr1);
    cudaGetSymbolAddress((void**)&h1,  g_h1);
    cudaGetSymbolAddress((void**)&xl2, g_xl2);
    cudaGetSymbolAddress((void**)&xr2, g_xr2);
    cudaGetSymbolAddress((void**)&h2,  g_h2);

    // 1) KNN graph
    knn_kernel<<<dim3(NN / 256, BB), 256>>>(pos);

    // 2) Layer-1 transforms (grid.y: 0 -> Wl/xl, 1 -> Wr/xr), attention, ReLU
    gemm_kernel<F1, D1><<<dim3(BB * NN / 128, 2), 256>>>(
        x, Wl1, bl1, Wr1, br1, xl1, xr1);
    attn_kernel<16, D1><<<(BB * NN * 32) / 256, 256>>>(xl1, xr1, att1, bias1, h1);

    // 3) Layer-2 transforms, attention, ReLU
    gemm_kernel<D1, D2><<<dim3(BB * NN / 128, 2), 256>>>(
        h1, Wl2, bl2, Wr2, br2, xl2, xr2);
    attn_kernel<32, D2><<<(BB * NN * 32) / 256, 256>>>(xl2, xr2, att2, bias2, h2);

    // 4) Global mean pool
    pool_kernel<<<BB, 512>>>(h2, out);
}